// round 5
// baseline (speedup 1.0000x reference)
#include <cuda_runtime.h>
#include <math.h>

// Problem: T = D = 4096 throughout.
//   q = x@Wq + bq ; k = x@Wk + bk ; v = x@Wv + bv      (NN GEMM + bias)
//   S = (q @ k^T) * 1/64                               (NT GEMM, alpha)
//   P = softmax_rows(S)
//   out = P @ v^T                                      (NT GEMM)
#define TT 4096

// Scratch (no cudaMalloc allowed): 4 x 64 MB fp32
__device__ float g_q[(size_t)TT * TT];
__device__ float g_k[(size_t)TT * TT];
__device__ float g_v[(size_t)TT * TT];
__device__ float g_s[(size_t)TT * TT];

// ---------------------------------------------------------------------------
// Tiled SGEMM: C[M,N] = alpha * A[M,K] @ op(B) (+ bias[N])
//   TRANSB=false : B is [K,N] row-major (NN)
//   TRANSB=true  : B is [N,K] row-major (NT, i.e. C = A @ B^T)
// BM=BN=128, BK=16, 256 threads, 8x8 per thread. M,N,K multiples of 128/16.
// ---------------------------------------------------------------------------
template <bool TRANSB, bool HASBIAS>
__global__ void __launch_bounds__(256, 2)
sgemm_kernel(const float* __restrict__ A, const float* __restrict__ B,
             const float* __restrict__ bias, float* __restrict__ C,
             int M, int N, int K, float alpha)
{
    constexpr int BM = 128, BN = 128, BK = 16;
    __shared__ float As[BK][BM];
    __shared__ float Bs[BK][BN];

    const int tid = threadIdx.x;
    const int tx  = tid & 15;   // n-direction (0..15)
    const int ty  = tid >> 4;   // m-direction (0..15)
    const int bm0 = blockIdx.y * BM;
    const int bn0 = blockIdx.x * BN;

    float acc[8][8];
#pragma unroll
    for (int i = 0; i < 8; i++)
#pragma unroll
        for (int j = 0; j < 8; j++) acc[i][j] = 0.0f;

    for (int k0 = 0; k0 < K; k0 += BK) {
        // --- load A tile [BM x BK], store transposed into As[k][m] ---
#pragma unroll
        for (int l = 0; l < 2; l++) {
            int idx = tid + l * 256;        // 0..511
            int row = idx >> 2;             // 0..127
            int c4  = (idx & 3) << 2;       // 0,4,8,12
            const float4 va = *reinterpret_cast<const float4*>(
                &A[(size_t)(bm0 + row) * K + k0 + c4]);
            As[c4 + 0][row] = va.x;
            As[c4 + 1][row] = va.y;
            As[c4 + 2][row] = va.z;
            As[c4 + 3][row] = va.w;
        }
        // --- load B tile into Bs[k][n] ---
        if (!TRANSB) {
#pragma unroll
            for (int l = 0; l < 2; l++) {
                int idx = tid + l * 256;
                int kk  = idx >> 5;              // 0..15
                int c4  = (idx & 31) << 2;       // 0..124
                *reinterpret_cast<float4*>(&Bs[kk][c4]) =
                    *reinterpret_cast<const float4*>(
                        &B[(size_t)(k0 + kk) * N + bn0 + c4]);
            }
        } else {
#pragma unroll
            for (int l = 0; l < 2; l++) {
                int idx = tid + l * 256;
                int n   = idx >> 2;              // 0..127
                int c4  = (idx & 3) << 2;        // 0,4,8,12
                const float4 vb = *reinterpret_cast<const float4*>(
                    &B[(size_t)(bn0 + n) * K + k0 + c4]);
                Bs[c4 + 0][n] = vb.x;
                Bs[c4 + 1][n] = vb.y;
                Bs[c4 + 2][n] = vb.z;
                Bs[c4 + 3][n] = vb.w;
            }
        }
        __syncthreads();

        // --- compute ---
#pragma unroll
        for (int k = 0; k < BK; k++) {
            float a[8], b[8];
            *reinterpret_cast<float4*>(&a[0]) =
                *reinterpret_cast<const float4*>(&As[k][ty * 8]);
            *reinterpret_cast<float4*>(&a[4]) =
                *reinterpret_cast<const float4*>(&As[k][ty * 8 + 4]);
            *reinterpret_cast<float4*>(&b[0]) =
                *reinterpret_cast<const float4*>(&Bs[k][tx * 8]);
            *reinterpret_cast<float4*>(&b[4]) =
                *reinterpret_cast<const float4*>(&Bs[k][tx * 8 + 4]);
#pragma unroll
            for (int i = 0; i < 8; i++)
#pragma unroll
                for (int j = 0; j < 8; j++)
                    acc[i][j] = fmaf(a[i], b[j], acc[i][j]);
        }
        __syncthreads();
    }

    // --- epilogue ---
    float bvreg[8];
    if (HASBIAS) {
#pragma unroll
        for (int j = 0; j < 8; j++) bvreg[j] = bias[bn0 + tx * 8 + j];
    }
#pragma unroll
    for (int i = 0; i < 8; i++) {
        const size_t off = (size_t)(bm0 + ty * 8 + i) * N + bn0 + tx * 8;
        float4 o0, o1;
        o0.x = acc[i][0] * alpha + (HASBIAS ? bvreg[0] : 0.0f);
        o0.y = acc[i][1] * alpha + (HASBIAS ? bvreg[1] : 0.0f);
        o0.z = acc[i][2] * alpha + (HASBIAS ? bvreg[2] : 0.0f);
        o0.w = acc[i][3] * alpha + (HASBIAS ? bvreg[3] : 0.0f);
        o1.x = acc[i][4] * alpha + (HASBIAS ? bvreg[4] : 0.0f);
        o1.y = acc[i][5] * alpha + (HASBIAS ? bvreg[5] : 0.0f);
        o1.z = acc[i][6] * alpha + (HASBIAS ? bvreg[6] : 0.0f);
        o1.w = acc[i][7] * alpha + (HASBIAS ? bvreg[7] : 0.0f);
        *reinterpret_cast<float4*>(&C[off])     = o0;
        *reinterpret_cast<float4*>(&C[off + 4]) = o1;
    }
}

// ---------------------------------------------------------------------------
// Row softmax over [TT, TT], in place. One block (256 threads) per row;
// each thread holds its 16 elements in registers (single global read/write).
// ---------------------------------------------------------------------------
__global__ void __launch_bounds__(256)
softmax_rows_kernel(float* __restrict__ S)
{
    const int row = blockIdx.x;
    float4* p = reinterpret_cast<float4*>(S + (size_t)row * TT);
    const int tid = threadIdx.x;

    float4 r[4];
    float m = -3.402823466e38f;
#pragma unroll
    for (int w = 0; w < 4; w++) {
        r[w] = p[tid + w * 256];
        m = fmaxf(m, fmaxf(fmaxf(r[w].x, r[w].y), fmaxf(r[w].z, r[w].w)));
    }
    // warp-reduce max
#pragma unroll
    for (int o = 16; o > 0; o >>= 1)
        m = fmaxf(m, __shfl_xor_sync(0xffffffffu, m, o));

    __shared__ float sm_max[8];
    __shared__ float sm_sum[8];
    const int wid = tid >> 5;
    const int lid = tid & 31;
    if (lid == 0) sm_max[wid] = m;
    __syncthreads();
    float bm = sm_max[0];
#pragma unroll
    for (int i = 1; i < 8; i++) bm = fmaxf(bm, sm_max[i]);

    float s = 0.0f;
#pragma unroll
    for (int w = 0; w < 4; w++) {
        r[w].x = __expf(r[w].x - bm);
        r[w].y = __expf(r[w].y - bm);
        r[w].z = __expf(r[w].z - bm);
        r[w].w = __expf(r[w].w - bm);
        s += r[w].x + r[w].y + r[w].z + r[w].w;
    }
#pragma unroll
    for (int o = 16; o > 0; o >>= 1)
        s += __shfl_xor_sync(0xffffffffu, s, o);
    if (lid == 0) sm_sum[wid] = s;
    __syncthreads();
    float bs = 0.0f;
#pragma unroll
    for (int i = 0; i < 8; i++) bs += sm_sum[i];
    const float inv = 1.0f / bs;

#pragma unroll
    for (int w = 0; w < 4; w++) {
        r[w].x *= inv; r[w].y *= inv; r[w].z *= inv; r[w].w *= inv;
        p[tid + w * 256] = r[w];
    }
}

// ---------------------------------------------------------------------------
extern "C" void kernel_launch(void* const* d_in, const int* in_sizes, int n_in,
                              void* d_out, int out_size)
{
    (void)in_sizes; (void)n_in; (void)out_size;
    const float* x  = (const float*)d_in[0];
    const float* Wq = (const float*)d_in[1];
    const float* bq = (const float*)d_in[2];
    const float* Wk = (const float*)d_in[3];
    const float* bk = (const float*)d_in[4];
    const float* Wv = (const float*)d_in[5];
    const float* bv = (const float*)d_in[6];
    float* out = (float*)d_out;

    float *qp, *kp, *vp, *sp;
    cudaGetSymbolAddress((void**)&qp, g_q);
    cudaGetSymbolAddress((void**)&kp, g_k);
    cudaGetSymbolAddress((void**)&vp, g_v);
    cudaGetSymbolAddress((void**)&sp, g_s);

    const dim3 grid(TT / 128, TT / 128);
    const dim3 block(256);
    const float scale = 1.0f / 64.0f;  // 1/sqrt(4096)

    // QKV projections (NN + bias)
    sgemm_kernel<false, true><<<grid, block>>>(x, Wq, bq, qp, TT, TT, TT, 1.0f);
    sgemm_kernel<false, true><<<grid, block>>>(x, Wk, bk, kp, TT, TT, TT, 1.0f);
    sgemm_kernel<false, true><<<grid, block>>>(x, Wv, bv, vp, TT, TT, TT, 1.0f);
    // S = scale * q @ k^T   (NT)
    sgemm_kernel<true, false><<<grid, block>>>(qp, kp, nullptr, sp, TT, TT, TT, scale);
    // P = softmax_rows(S)
    softmax_rows_kernel<<<TT, block>>>(sp);
    // out = P @ v^T         (NT)
    sgemm_kernel<true, false><<<grid, block>>>(sp, vp, nullptr, out, TT, TT, TT, 1.0f);
}

// round 11
// speedup vs baseline: 3.3183x; 3.3183x over previous
#include <cuda_runtime.h>
#include <cuda_bf16.h>
#include <stdint.h>
#include <math.h>

#define TT 4096
typedef __nv_bfloat16 bf16;

// ---------------------------------------------------------------------------
// Scratch (__device__ globals; no cudaMalloc allowed)
// ---------------------------------------------------------------------------
__device__ __align__(128) float g_s [(size_t)TT * TT];   // scores fp32 (64MB)
__device__ __align__(128) bf16  g_xh[(size_t)TT * TT];
__device__ __align__(128) bf16  g_xl[(size_t)TT * TT];
__device__ __align__(128) bf16  g_wth[(size_t)TT * TT];  // W^T hi (reused per proj)
__device__ __align__(128) bf16  g_wtl[(size_t)TT * TT];
__device__ __align__(128) bf16  g_qh[(size_t)TT * TT];   // q, later P
__device__ __align__(128) bf16  g_ql[(size_t)TT * TT];
__device__ __align__(128) bf16  g_kh[(size_t)TT * TT];
__device__ __align__(128) bf16  g_kl[(size_t)TT * TT];
__device__ __align__(128) bf16  g_vh[(size_t)TT * TT];
__device__ __align__(128) bf16  g_vl[(size_t)TT * TT];

// ---------------------------------------------------------------------------
// helpers
// ---------------------------------------------------------------------------
__device__ __forceinline__ uint32_t smem_to_u32(const void* p) {
    uint32_t a;
    asm("{ .reg .u64 t; cvta.to.shared.u64 t, %1; cvt.u32.u64 %0, t; }"
        : "=r"(a) : "l"(p));
    return a;
}
__device__ __forceinline__ uint32_t sw128(uint32_t bo) { return bo ^ ((bo >> 3) & 0x70); }

__device__ __forceinline__ void split_bf16(float v, bf16& h, bf16& l) {
    h = __float2bfloat16(v);
    l = __float2bfloat16(v - __bfloat162float(h));
}
__device__ __forceinline__ uint32_t pack2(bf16 a, bf16 b) {
    return (uint32_t)__bfloat16_as_ushort(a) | ((uint32_t)__bfloat16_as_ushort(b) << 16);
}

#define CP_ASYNC16(saddr, gptr) \
    asm volatile("cp.async.cg.shared.global [%0], [%1], 16;" \
                 :: "r"(saddr), "l"(gptr) : "memory")
#define CP_COMMIT() asm volatile("cp.async.commit_group;" ::: "memory")
#define CP_WAIT1()  asm volatile("cp.async.wait_group 1;"  ::: "memory")

#define LDMATRIX_X4(r0, r1, r2, r3, addr) \
    asm volatile("ldmatrix.sync.aligned.m8n8.x4.shared.b16 {%0,%1,%2,%3}, [%4];" \
                 : "=r"(r0), "=r"(r1), "=r"(r2), "=r"(r3) : "r"(addr))

#define MMA_BF16(d, a, b0, b1) \
    asm volatile("mma.sync.aligned.m16n8k16.row.col.f32.bf16.bf16.f32 " \
                 "{%0,%1,%2,%3}, {%4,%5,%6,%7}, {%8,%9}, {%0,%1,%2,%3};" \
                 : "+f"((d)[0]), "+f"((d)[1]), "+f"((d)[2]), "+f"((d)[3]) \
                 : "r"((a)[0]), "r"((a)[1]), "r"((a)[2]), "r"((a)[3]), \
                   "r"(b0), "r"(b1))

// ---------------------------------------------------------------------------
// Elementwise split: x fp32 -> xh, xl
// ---------------------------------------------------------------------------
__global__ void __launch_bounds__(256)
convert_split_kernel(const float* __restrict__ X, bf16* __restrict__ H, bf16* __restrict__ L)
{
    size_t j = (size_t)blockIdx.x * blockDim.x + threadIdx.x;   // float4 index
    const float4 v = reinterpret_cast<const float4*>(X)[j];
    bf16 h0, h1, h2, h3, l0, l1, l2, l3;
    split_bf16(v.x, h0, l0); split_bf16(v.y, h1, l1);
    split_bf16(v.z, h2, l2); split_bf16(v.w, h3, l3);
    uint2 uh; uh.x = pack2(h0, h1); uh.y = pack2(h2, h3);
    uint2 ul; ul.x = pack2(l0, l1); ul.y = pack2(l2, l3);
    reinterpret_cast<uint2*>(H)[j] = uh;
    reinterpret_cast<uint2*>(L)[j] = ul;
}

// ---------------------------------------------------------------------------
// Transpose + split: W [K,N] fp32 -> WT_hi/WT_lo [N,K] bf16
// ---------------------------------------------------------------------------
__global__ void __launch_bounds__(256)
transpose_split_kernel(const float* __restrict__ W, bf16* __restrict__ TH, bf16* __restrict__ TL)
{
    __shared__ float t[32][33];
    const int tx = threadIdx.x, ty = threadIdx.y;     // 32 x 8
    const int n0 = blockIdx.x * 32, k0 = blockIdx.y * 32;
#pragma unroll
    for (int l = 0; l < 4; l++)
        t[ty + 8 * l][tx] = W[(size_t)(k0 + ty + 8 * l) * TT + n0 + tx];
    __syncthreads();
#pragma unroll
    for (int l = 0; l < 4; l++) {
        float v = t[tx][ty + 8 * l];
        bf16 h, lo; split_bf16(v, h, lo);
        size_t off = (size_t)(n0 + ty + 8 * l) * TT + k0 + tx;
        TH[off] = h; TL[off] = lo;
    }
}

// ---------------------------------------------------------------------------
// NT GEMM, 3-pass bf16 split, mma.sync + cp.async 3-stage pipeline.
//   C = alpha * (A @ B^T) (+ bias),  A/B given as (hi,lo) bf16 K-major [TT,TT]
//   MODE 0: C -> (Ch, Cl) bf16 split with bias added
//   MODE 1: C -> Cf fp32 scaled by alpha
// CTA tile 128x128, BK=64, 256 threads (8 warps, 4x2), warp tile 32x64.
// ---------------------------------------------------------------------------
#define TILE_B   16384           // 128 rows * 128B per operand tile
#define STAGE_B  (4 * TILE_B)    // Ah, Al, Bh, Bl
#define NSTAGE   3
#define GEMM_SMEM (NSTAGE * STAGE_B)   // 196608

__device__ __forceinline__ void issue_stage_loads(
    const bf16* __restrict__ Ah, const bf16* __restrict__ Al,
    const bf16* __restrict__ Bh, const bf16* __restrict__ Bl,
    int bm0, int bn0, int k0, uint32_t stage_base, int tid)
{
    const bf16* srcs[4] = { Ah, Al, Bh, Bl };
    const int   row0[4] = { bm0, bm0, bn0, bn0 };
#pragma unroll
    for (int t = 0; t < 4; t++) {
        const bf16* G = srcs[t];
        const uint32_t tb = stage_base + t * TILE_B;
#pragma unroll
        for (int it = 0; it < 4; it++) {
            int idx = tid + it * 256;           // 0..1023
            int r = idx >> 3;                   // 0..127
            int c = idx & 7;                    // 16B chunk
            const bf16* gp = G + ((size_t)(row0[t] + r) << 12) + k0 + c * 8;
            uint32_t sa = tb + sw128((uint32_t)(r << 7) + (uint32_t)(c << 4));
            CP_ASYNC16(sa, gp);
        }
    }
}

template <int MODE>
__global__ void __launch_bounds__(256, 1)
gemm_bf16x3_kernel(const bf16* __restrict__ Ah, const bf16* __restrict__ Al,
                   const bf16* __restrict__ Bh, const bf16* __restrict__ Bl,
                   const float* __restrict__ bias, float alpha,
                   float* __restrict__ Cf, bf16* __restrict__ Ch, bf16* __restrict__ Cl)
{
    extern __shared__ char smem[];
    const uint32_t sb = smem_to_u32(smem);
    const int tid  = threadIdx.x;
    const int wid  = tid >> 5;
    const int lane = tid & 31;
    const int bm0 = blockIdx.y * 128, bn0 = blockIdx.x * 128;
    const int wm = (wid & 3) * 32;        // warp m offset in tile
    const int wn = (wid >> 2) * 64;       // warp n offset in tile

    float acc[2][8][4];
#pragma unroll
    for (int mi = 0; mi < 2; mi++)
#pragma unroll
        for (int nj = 0; nj < 8; nj++)
#pragma unroll
            for (int e = 0; e < 4; e++) acc[mi][nj][e] = 0.0f;

    // prologue: stages 0, 1
    issue_stage_loads(Ah, Al, Bh, Bl, bm0, bn0, 0,  sb,            tid); CP_COMMIT();
    issue_stage_loads(Ah, Al, Bh, Bl, bm0, bn0, 64, sb + STAGE_B,  tid); CP_COMMIT();

    // per-lane ldmatrix address components (byte offsets within a 128x128B tile)
    const int a_row = (lane & 15);
    const int a_cb  = (lane >> 4) << 4;                 // 0 or 16
    const int b_row = (lane & 7) + ((lane >> 4) << 3);  // 0..15
    const int b_cb  = ((lane >> 3) & 1) << 4;           // 0 or 16

    for (int c = 0; c < 64; c++) {
        CP_WAIT1();
        __syncthreads();

        // issue loads for stage c+2 (buffer (c+2)%3, consumed at iter c-1)
        if (c + 2 < 64) {
            issue_stage_loads(Ah, Al, Bh, Bl, bm0, bn0, (c + 2) * 64,
                              sb + ((c + 2) % NSTAGE) * STAGE_B, tid);
        }
        CP_COMMIT();

        const uint32_t stage = sb + (c % NSTAGE) * STAGE_B;
        const uint32_t tAh = stage;
        const uint32_t tAl = stage + TILE_B;
        const uint32_t tBh = stage + 2 * TILE_B;
        const uint32_t tBl = stage + 3 * TILE_B;

#pragma unroll
        for (int ks = 0; ks < 4; ks++) {
            const int kcb = ks * 32;
            uint32_t ah[2][4], al[2][4];
#pragma unroll
            for (int mi = 0; mi < 2; mi++) {
                const uint32_t ro = (uint32_t)((wm + mi * 16 + a_row) << 7);
                const uint32_t co = (uint32_t)(kcb + a_cb);
                LDMATRIX_X4(ah[mi][0], ah[mi][1], ah[mi][2], ah[mi][3],
                            tAh + sw128(ro + co));
                LDMATRIX_X4(al[mi][0], al[mi][1], al[mi][2], al[mi][3],
                            tAl + sw128(ro + co));
            }
            uint32_t bh[4][4], bl[4][4];
#pragma unroll
            for (int ni = 0; ni < 4; ni++) {
                const uint32_t ro = (uint32_t)((wn + ni * 16 + b_row) << 7);
                const uint32_t co = (uint32_t)(kcb + b_cb);
                LDMATRIX_X4(bh[ni][0], bh[ni][1], bh[ni][2], bh[ni][3],
                            tBh + sw128(ro + co));
                LDMATRIX_X4(bl[ni][0], bl[ni][1], bl[ni][2], bl[ni][3],
                            tBl + sw128(ro + co));
            }
#pragma unroll
            for (int mi = 0; mi < 2; mi++) {
#pragma unroll
                for (int nj = 0; nj < 8; nj++) {
                    const int ni = nj >> 1, s = (nj & 1) << 1;
                    MMA_BF16(acc[mi][nj], ah[mi], bh[ni][s], bh[ni][s + 1]);
                    MMA_BF16(acc[mi][nj], ah[mi], bl[ni][s], bl[ni][s + 1]);
                    MMA_BF16(acc[mi][nj], al[mi], bh[ni][s], bh[ni][s + 1]);
                }
            }
        }
        __syncthreads();
    }

    // ---- epilogue: direct stores from fragments ----
#pragma unroll
    for (int mi = 0; mi < 2; mi++) {
#pragma unroll
        for (int nj = 0; nj < 8; nj++) {
            const int row = bm0 + wm + mi * 16 + (lane >> 2);
            const int col = bn0 + wn + nj * 8 + (lane & 3) * 2;
            if (MODE == 0) {
                const float b0 = bias[col], b1 = bias[col + 1];
#pragma unroll
                for (int h = 0; h < 2; h++) {      // row, row+8
                    const float v0 = acc[mi][nj][2 * h + 0] + b0;
                    const float v1 = acc[mi][nj][2 * h + 1] + b1;
                    bf16 h0, h1, l0, l1;
                    split_bf16(v0, h0, l0); split_bf16(v1, h1, l1);
                    const size_t off = (size_t)(row + 8 * h) * TT + col;
                    *reinterpret_cast<uint32_t*>(Ch + off) = pack2(h0, h1);
                    *reinterpret_cast<uint32_t*>(Cl + off) = pack2(l0, l1);
                }
            } else {
#pragma unroll
                for (int h = 0; h < 2; h++) {
                    float2 v;
                    v.x = acc[mi][nj][2 * h + 0] * alpha;
                    v.y = acc[mi][nj][2 * h + 1] * alpha;
                    *reinterpret_cast<float2*>(Cf + (size_t)(row + 8 * h) * TT + col) = v;
                }
            }
        }
    }
}

// ---------------------------------------------------------------------------
// Row softmax over S [TT,TT] fp32; emits P as (hi, lo) bf16.
// ---------------------------------------------------------------------------
__global__ void __launch_bounds__(256)
softmax_rows_kernel(const float* __restrict__ S, bf16* __restrict__ PH, bf16* __restrict__ PL)
{
    const int row = blockIdx.x;
    const float4* p = reinterpret_cast<const float4*>(S + (size_t)row * TT);
    const int tid = threadIdx.x;

    float4 r[4];
    float m = -3.402823466e38f;
#pragma unroll
    for (int w = 0; w < 4; w++) {
        r[w] = p[tid + w * 256];
        m = fmaxf(m, fmaxf(fmaxf(r[w].x, r[w].y), fmaxf(r[w].z, r[w].w)));
    }
#pragma unroll
    for (int o = 16; o > 0; o >>= 1)
        m = fmaxf(m, __shfl_xor_sync(0xffffffffu, m, o));

    __shared__ float sm_max[8], sm_sum[8];
    const int wid = tid >> 5, lid = tid & 31;
    if (lid == 0) sm_max[wid] = m;
    __syncthreads();
    float bm = sm_max[0];
#pragma unroll
    for (int i = 1; i < 8; i++) bm = fmaxf(bm, sm_max[i]);

    float s = 0.0f;
#pragma unroll
    for (int w = 0; w < 4; w++) {
        r[w].x = __expf(r[w].x - bm);
        r[w].y = __expf(r[w].y - bm);
        r[w].z = __expf(r[w].z - bm);
        r[w].w = __expf(r[w].w - bm);
        s += r[w].x + r[w].y + r[w].z + r[w].w;
    }
#pragma unroll
    for (int o = 16; o > 0; o >>= 1)
        s += __shfl_xor_sync(0xffffffffu, s, o);
    if (lid == 0) sm_sum[wid] = s;
    __syncthreads();
    float bs = 0.0f;
#pragma unroll
    for (int i = 0; i < 8; i++) bs += sm_sum[i];
    const float inv = 1.0f / bs;

#pragma unroll
    for (int w = 0; w < 4; w++) {
        float v0 = r[w].x * inv, v1 = r[w].y * inv, v2 = r[w].z * inv, v3 = r[w].w * inv;
        bf16 h0, h1, h2, h3, l0, l1, l2, l3;
        split_bf16(v0, h0, l0); split_bf16(v1, h1, l1);
        split_bf16(v2, h2, l2); split_bf16(v3, h3, l3);
        uint2 uh; uh.x = pack2(h0, h1); uh.y = pack2(h2, h3);
        uint2 ul; ul.x = pack2(l0, l1); ul.y = pack2(l2, l3);
        const size_t off = (size_t)row * TT + (size_t)(tid + w * 256) * 4;
        *reinterpret_cast<uint2*>(PH + off) = uh;
        *reinterpret_cast<uint2*>(PL + off) = ul;
    }
}

// ---------------------------------------------------------------------------
extern "C" void kernel_launch(void* const* d_in, const int* in_sizes, int n_in,
                              void* d_out, int out_size)
{
    (void)in_sizes; (void)n_in; (void)out_size;
    const float* x  = (const float*)d_in[0];
    const float* Wq = (const float*)d_in[1];
    const float* bq = (const float*)d_in[2];
    const float* Wk = (const float*)d_in[3];
    const float* bk = (const float*)d_in[4];
    const float* Wv = (const float*)d_in[5];
    const float* bv = (const float*)d_in[6];
    float* out = (float*)d_out;

    float *sp;
    bf16 *xh, *xl, *wth, *wtl, *qh, *ql, *kh, *kl, *vh, *vl;
    cudaGetSymbolAddress((void**)&sp,  g_s);
    cudaGetSymbolAddress((void**)&xh,  g_xh);
    cudaGetSymbolAddress((void**)&xl,  g_xl);
    cudaGetSymbolAddress((void**)&wth, g_wth);
    cudaGetSymbolAddress((void**)&wtl, g_wtl);
    cudaGetSymbolAddress((void**)&qh,  g_qh);
    cudaGetSymbolAddress((void**)&ql,  g_ql);
    cudaGetSymbolAddress((void**)&kh,  g_kh);
    cudaGetSymbolAddress((void**)&kl,  g_kl);
    cudaGetSymbolAddress((void**)&vh,  g_vh);
    cudaGetSymbolAddress((void**)&vl,  g_vl);

    cudaFuncSetAttribute(gemm_bf16x3_kernel<0>,
                         cudaFuncAttributeMaxDynamicSharedMemorySize, GEMM_SMEM);
    cudaFuncSetAttribute(gemm_bf16x3_kernel<1>,
                         cudaFuncAttributeMaxDynamicSharedMemorySize, GEMM_SMEM);

    const dim3 ggrid(TT / 128, TT / 128);   // 32 x 32
    const dim3 tgrid(TT / 32, TT / 32);     // 128 x 128
    const dim3 tblk(32, 8);
    const float scale = 1.0f / 64.0f;       // 1/sqrt(4096)

    // split x
    convert_split_kernel<<<(TT * (size_t)TT) / 4 / 256, 256>>>(x, xh, xl);

    // q = x @ Wq + bq
    transpose_split_kernel<<<tgrid, tblk>>>(Wq, wth, wtl);
    gemm_bf16x3_kernel<0><<<ggrid, 256, GEMM_SMEM>>>(xh, xl, wth, wtl, bq, 1.0f,
                                                     nullptr, qh, ql);
    // k = x @ Wk + bk
    transpose_split_kernel<<<tgrid, tblk>>>(Wk, wth, wtl);
    gemm_bf16x3_kernel<0><<<ggrid, 256, GEMM_SMEM>>>(xh, xl, wth, wtl, bk, 1.0f,
                                                     nullptr, kh, kl);
    // v = x @ Wv + bv
    transpose_split_kernel<<<tgrid, tblk>>>(Wv, wth, wtl);
    gemm_bf16x3_kernel<0><<<ggrid, 256, GEMM_SMEM>>>(xh, xl, wth, wtl, bv, 1.0f,
                                                     nullptr, vh, vl);
    // S = scale * q @ k^T
    gemm_bf16x3_kernel<1><<<ggrid, 256, GEMM_SMEM>>>(qh, ql, kh, kl, nullptr, scale,
                                                     sp, nullptr, nullptr);
    // P = softmax_rows(S) -> (qh, ql) reused as P hi/lo
    softmax_rows_kernel<<<TT, 256>>>(sp, qh, ql);
    // out = P @ v^T
    gemm_bf16x3_kernel<1><<<ggrid, 256, GEMM_SMEM>>>(qh, ql, vh, vl, nullptr, 1.0f,
                                                     out, nullptr, nullptr);
}

// round 12
// speedup vs baseline: 3.3784x; 1.0181x over previous
#include <cuda_runtime.h>
#include <cuda_bf16.h>
#include <stdint.h>
#include <math.h>

#define TT 4096
#define SZ ((size_t)TT * TT)
typedef __nv_bfloat16 bf16;

// ---------------------------------------------------------------------------
// Scratch (__device__ globals; no cudaMalloc allowed)
// ---------------------------------------------------------------------------
__device__ __align__(128) float g_s [SZ];        // scores fp32 (64MB)
__device__ __align__(128) bf16  g_xh[SZ];
__device__ __align__(128) bf16  g_xl[SZ];
__device__ __align__(128) bf16  g_wh[3][SZ];     // Wq^T,Wk^T,Wv^T hi
__device__ __align__(128) bf16  g_wl[3][SZ];     // lo
__device__ __align__(128) bf16  g_oh[3][SZ];     // q,k,v hi (q slab reused as P)
__device__ __align__(128) bf16  g_ol[3][SZ];     // lo

// ---------------------------------------------------------------------------
// helpers
// ---------------------------------------------------------------------------
__device__ __forceinline__ uint32_t smem_to_u32(const void* p) {
    uint32_t a;
    asm("{ .reg .u64 t; cvta.to.shared.u64 t, %1; cvt.u32.u64 %0, t; }"
        : "=r"(a) : "l"(p));
    return a;
}
__device__ __forceinline__ uint32_t sw128(uint32_t bo) { return bo ^ ((bo >> 3) & 0x70); }

__device__ __forceinline__ void split_bf16(float v, bf16& h, bf16& l) {
    h = __float2bfloat16(v);
    l = __float2bfloat16(v - __bfloat162float(h));
}
__device__ __forceinline__ uint32_t pack2(bf16 a, bf16 b) {
    return (uint32_t)__bfloat16_as_ushort(a) | ((uint32_t)__bfloat16_as_ushort(b) << 16);
}

#define CP_ASYNC16(saddr, gptr) \
    asm volatile("cp.async.cg.shared.global [%0], [%1], 16;" \
                 :: "r"(saddr), "l"(gptr) : "memory")
#define CP_COMMIT() asm volatile("cp.async.commit_group;" ::: "memory")
#define CP_WAIT1()  asm volatile("cp.async.wait_group 1;"  ::: "memory")

#define LDMATRIX_X4(r0, r1, r2, r3, addr) \
    asm volatile("ldmatrix.sync.aligned.m8n8.x4.shared.b16 {%0,%1,%2,%3}, [%4];" \
                 : "=r"(r0), "=r"(r1), "=r"(r2), "=r"(r3) : "r"(addr))

#define MMA_BF16(d, a, b0, b1) \
    asm volatile("mma.sync.aligned.m16n8k16.row.col.f32.bf16.bf16.f32 " \
                 "{%0,%1,%2,%3}, {%4,%5,%6,%7}, {%8,%9}, {%0,%1,%2,%3};" \
                 : "+f"((d)[0]), "+f"((d)[1]), "+f"((d)[2]), "+f"((d)[3]) \
                 : "r"((a)[0]), "r"((a)[1]), "r"((a)[2]), "r"((a)[3]), \
                   "r"(b0), "r"(b1))

// ---------------------------------------------------------------------------
// Elementwise split: x fp32 -> xh, xl
// ---------------------------------------------------------------------------
__global__ void __launch_bounds__(256)
convert_split_kernel(const float* __restrict__ X, bf16* __restrict__ H, bf16* __restrict__ L)
{
    size_t j = (size_t)blockIdx.x * blockDim.x + threadIdx.x;   // float4 index
    const float4 v = reinterpret_cast<const float4*>(X)[j];
    bf16 h0, h1, h2, h3, l0, l1, l2, l3;
    split_bf16(v.x, h0, l0); split_bf16(v.y, h1, l1);
    split_bf16(v.z, h2, l2); split_bf16(v.w, h3, l3);
    uint2 uh; uh.x = pack2(h0, h1); uh.y = pack2(h2, h3);
    uint2 ul; ul.x = pack2(l0, l1); ul.y = pack2(l2, l3);
    reinterpret_cast<uint2*>(H)[j] = uh;
    reinterpret_cast<uint2*>(L)[j] = ul;
}

// ---------------------------------------------------------------------------
// Fused 3-way transpose + split: W[z] [K,N] fp32 -> WT hi/lo [N,K] bf16
// ---------------------------------------------------------------------------
__global__ void __launch_bounds__(256)
transpose_split3_kernel(const float* __restrict__ W0, const float* __restrict__ W1,
                        const float* __restrict__ W2,
                        bf16* __restrict__ THb, bf16* __restrict__ TLb)
{
    const int z = blockIdx.z;
    const float* W = (z == 0) ? W0 : (z == 1) ? W1 : W2;
    bf16* TH = THb + (size_t)z * SZ;
    bf16* TL = TLb + (size_t)z * SZ;

    __shared__ float t[32][33];
    const int tx = threadIdx.x, ty = threadIdx.y;     // 32 x 8
    const int n0 = blockIdx.x * 32, k0 = blockIdx.y * 32;
#pragma unroll
    for (int l = 0; l < 4; l++)
        t[ty + 8 * l][tx] = W[(size_t)(k0 + ty + 8 * l) * TT + n0 + tx];
    __syncthreads();
#pragma unroll
    for (int l = 0; l < 4; l++) {
        float v = t[tx][ty + 8 * l];
        bf16 h, lo; split_bf16(v, h, lo);
        size_t off = (size_t)(n0 + ty + 8 * l) * TT + k0 + tx;
        TH[off] = h; TL[off] = lo;
    }
}

// ---------------------------------------------------------------------------
// NT GEMM, 3-pass bf16 split, mma.sync + cp.async 3-stage pipeline.
//   C = alpha * (A @ B^T) (+ bias);  B/bias/C selected by blockIdx.z
//   MODE 0: C -> (Ch, Cl) bf16 split with bias added
//   MODE 1: C -> Cf fp32 scaled by alpha
// CTA tile 128x128, BK=64, 256 threads (8 warps, 4x2), warp tile 32x64.
// Pass-major MMA ordering + fragment double-buffering + GROUP_M=8 raster.
// ---------------------------------------------------------------------------
#define TILE_B   16384           // 128 rows * 128B per operand tile
#define STAGE_B  (4 * TILE_B)    // Ah, Al, Bh, Bl
#define NSTAGE   3
#define GEMM_SMEM (NSTAGE * STAGE_B)   // 196608

__device__ __forceinline__ void issue_stage_loads(
    const bf16* __restrict__ Ah, const bf16* __restrict__ Al,
    const bf16* __restrict__ Bh, const bf16* __restrict__ Bl,
    int bm0, int bn0, int k0, uint32_t stage_base, int tid)
{
    const bf16* srcs[4] = { Ah, Al, Bh, Bl };
    const int   row0[4] = { bm0, bm0, bn0, bn0 };
#pragma unroll
    for (int t = 0; t < 4; t++) {
        const bf16* G = srcs[t];
        const uint32_t tb = stage_base + t * TILE_B;
#pragma unroll
        for (int it = 0; it < 4; it++) {
            int idx = tid + it * 256;           // 0..1023
            int r = idx >> 3;                   // 0..127
            int c = idx & 7;                    // 16B chunk
            const bf16* gp = G + ((size_t)(row0[t] + r) << 12) + k0 + c * 8;
            uint32_t sa = tb + sw128((uint32_t)(r << 7) + (uint32_t)(c << 4));
            CP_ASYNC16(sa, gp);
        }
    }
}

// load all hi/lo fragments of one k16 step into register buffer `buf`
#define LOAD_FRAGS(stageaddr, ks, buf) do {                                   \
    const int _kcb = (ks) * 32;                                               \
    const uint32_t _tAh = (stageaddr);                                        \
    const uint32_t _tAl = (stageaddr) + TILE_B;                               \
    const uint32_t _tBh = (stageaddr) + 2 * TILE_B;                           \
    const uint32_t _tBl = (stageaddr) + 3 * TILE_B;                           \
    _Pragma("unroll")                                                         \
    for (int _mi = 0; _mi < 2; _mi++) {                                       \
        const uint32_t _ro = (uint32_t)((wm + _mi * 16 + a_row) << 7);        \
        const uint32_t _co = (uint32_t)(_kcb + a_cb);                         \
        LDMATRIX_X4(ah[buf][_mi][0], ah[buf][_mi][1], ah[buf][_mi][2],        \
                    ah[buf][_mi][3], _tAh + sw128(_ro + _co));                \
        LDMATRIX_X4(al[buf][_mi][0], al[buf][_mi][1], al[buf][_mi][2],        \
                    al[buf][_mi][3], _tAl + sw128(_ro + _co));                \
    }                                                                         \
    _Pragma("unroll")                                                         \
    for (int _ni = 0; _ni < 4; _ni++) {                                       \
        const uint32_t _ro = (uint32_t)((wn + _ni * 16 + b_row) << 7);        \
        const uint32_t _co = (uint32_t)(_kcb + b_cb);                         \
        LDMATRIX_X4(bhf[buf][_ni][0], bhf[buf][_ni][1], bhf[buf][_ni][2],     \
                    bhf[buf][_ni][3], _tBh + sw128(_ro + _co));               \
        LDMATRIX_X4(blf[buf][_ni][0], blf[buf][_ni][1], blf[buf][_ni][2],     \
                    blf[buf][_ni][3], _tBl + sw128(_ro + _co));               \
    }                                                                         \
} while (0)

// 48 MMAs, pass-major: dependent MMAs on the same acc are 16 issues apart
#define MMA_BLOCK(buf) do {                                                   \
    _Pragma("unroll")                                                         \
    for (int _mi = 0; _mi < 2; _mi++)                                         \
    _Pragma("unroll")                                                         \
    for (int _nj = 0; _nj < 8; _nj++) {                                       \
        const int _ni = _nj >> 1, _s = (_nj & 1) << 1;                        \
        MMA_BF16(acc[_mi][_nj], ah[buf][_mi],                                 \
                 bhf[buf][_ni][_s], bhf[buf][_ni][_s + 1]);                   \
    }                                                                         \
    _Pragma("unroll")                                                         \
    for (int _mi = 0; _mi < 2; _mi++)                                         \
    _Pragma("unroll")                                                         \
    for (int _nj = 0; _nj < 8; _nj++) {                                       \
        const int _ni = _nj >> 1, _s = (_nj & 1) << 1;                        \
        MMA_BF16(acc[_mi][_nj], ah[buf][_mi],                                 \
                 blf[buf][_ni][_s], blf[buf][_ni][_s + 1]);                   \
    }                                                                         \
    _Pragma("unroll")                                                         \
    for (int _mi = 0; _mi < 2; _mi++)                                         \
    _Pragma("unroll")                                                         \
    for (int _nj = 0; _nj < 8; _nj++) {                                       \
        const int _ni = _nj >> 1, _s = (_nj & 1) << 1;                        \
        MMA_BF16(acc[_mi][_nj], al[buf][_mi],                                 \
                 bhf[buf][_ni][_s], bhf[buf][_ni][_s + 1]);                   \
    }                                                                         \
} while (0)

template <int MODE>
__global__ void __launch_bounds__(256, 1)
gemm_bf16x3_kernel(const bf16* __restrict__ Ah, const bf16* __restrict__ Al,
                   const bf16* __restrict__ BhB, const bf16* __restrict__ BlB,
                   const float* __restrict__ bias0, const float* __restrict__ bias1,
                   const float* __restrict__ bias2, float alpha,
                   float* __restrict__ Cf, bf16* __restrict__ ChB, bf16* __restrict__ ClB)
{
    extern __shared__ char smem[];
    const uint32_t sb = smem_to_u32(smem);
    const int tid  = threadIdx.x;
    const int wid  = tid >> 5;
    const int lane = tid & 31;

    const int z = blockIdx.z;
    const bf16* Bh = BhB + (size_t)z * SZ;
    const bf16* Bl = BlB + (size_t)z * SZ;
    const float* bias = (z == 0) ? bias0 : (z == 1) ? bias1 : bias2;
    bf16* Ch = (MODE == 0) ? (ChB + (size_t)z * SZ) : nullptr;
    bf16* Cl = (MODE == 0) ? (ClB + (size_t)z * SZ) : nullptr;

    // GROUP_M = 8 rasterization (grid is 32x32 per z-slice)
    const int bid = blockIdx.y * gridDim.x + blockIdx.x;     // 0..1023
    const int pm  = (bid >> 8) * 8 + (bid & 7);              // row tile
    const int pn  = (bid & 255) >> 3;                        // col tile
    const int bm0 = pm * 128, bn0 = pn * 128;

    const int wm = (wid & 3) * 32;        // warp m offset in tile
    const int wn = (wid >> 2) * 64;       // warp n offset in tile

    float acc[2][8][4];
#pragma unroll
    for (int mi = 0; mi < 2; mi++)
#pragma unroll
        for (int nj = 0; nj < 8; nj++)
#pragma unroll
            for (int e = 0; e < 4; e++) acc[mi][nj][e] = 0.0f;

    // prologue: stages 0, 1
    issue_stage_loads(Ah, Al, Bh, Bl, bm0, bn0, 0,  sb,           tid); CP_COMMIT();
    issue_stage_loads(Ah, Al, Bh, Bl, bm0, bn0, 64, sb + STAGE_B, tid); CP_COMMIT();

    // per-lane ldmatrix address components
    const int a_row = (lane & 15);
    const int a_cb  = (lane >> 4) << 4;                 // 0 or 16
    const int b_row = (lane & 7) + ((lane >> 4) << 3);  // 0..15
    const int b_cb  = ((lane >> 3) & 1) << 4;           // 0 or 16

    // fragment double buffers
    uint32_t ah[2][2][4], al[2][2][4], bhf[2][4][4], blf[2][4][4];

    for (int c = 0; c < 64; c++) {
        CP_WAIT1();
        __syncthreads();       // single barrier per chunk

        if (c + 2 < 64) {
            issue_stage_loads(Ah, Al, Bh, Bl, bm0, bn0, (c + 2) * 64,
                              sb + ((c + 2) % NSTAGE) * STAGE_B, tid);
        }
        CP_COMMIT();

        const uint32_t stage = sb + (c % NSTAGE) * STAGE_B;

        LOAD_FRAGS(stage, 0, 0);
        LOAD_FRAGS(stage, 1, 1);
        MMA_BLOCK(0);          // ks=0
        LOAD_FRAGS(stage, 2, 0);
        MMA_BLOCK(1);          // ks=1
        LOAD_FRAGS(stage, 3, 1);
        MMA_BLOCK(0);          // ks=2
        MMA_BLOCK(1);          // ks=3
    }

    // ---- epilogue: direct stores from fragments ----
#pragma unroll
    for (int mi = 0; mi < 2; mi++) {
#pragma unroll
        for (int nj = 0; nj < 8; nj++) {
            const int row = bm0 + wm + mi * 16 + (lane >> 2);
            const int col = bn0 + wn + nj * 8 + (lane & 3) * 2;
            if (MODE == 0) {
                const float b0 = bias[col], b1 = bias[col + 1];
#pragma unroll
                for (int h = 0; h < 2; h++) {      // row, row+8
                    const float v0 = acc[mi][nj][2 * h + 0] + b0;
                    const float v1 = acc[mi][nj][2 * h + 1] + b1;
                    bf16 h0, h1, l0, l1;
                    split_bf16(v0, h0, l0); split_bf16(v1, h1, l1);
                    const size_t off = (size_t)(row + 8 * h) * TT + col;
                    *reinterpret_cast<uint32_t*>(Ch + off) = pack2(h0, h1);
                    *reinterpret_cast<uint32_t*>(Cl + off) = pack2(l0, l1);
                }
            } else {
#pragma unroll
                for (int h = 0; h < 2; h++) {
                    float2 v;
                    v.x = acc[mi][nj][2 * h + 0] * alpha;
                    v.y = acc[mi][nj][2 * h + 1] * alpha;
                    *reinterpret_cast<float2*>(Cf + (size_t)(row + 8 * h) * TT + col) = v;
                }
            }
        }
    }
}

// ---------------------------------------------------------------------------
// Row softmax over S [TT,TT] fp32; emits P as (hi, lo) bf16.
// ---------------------------------------------------------------------------
__global__ void __launch_bounds__(256)
softmax_rows_kernel(const float* __restrict__ S, bf16* __restrict__ PH, bf16* __restrict__ PL)
{
    const int row = blockIdx.x;
    const float4* p = reinterpret_cast<const float4*>(S + (size_t)row * TT);
    const int tid = threadIdx.x;

    float4 r[4];
    float m = -3.402823466e38f;
#pragma unroll
    for (int w = 0; w < 4; w++) {
        r[w] = p[tid + w * 256];
        m = fmaxf(m, fmaxf(fmaxf(r[w].x, r[w].y), fmaxf(r[w].z, r[w].w)));
    }
#pragma unroll
    for (int o = 16; o > 0; o >>= 1)
        m = fmaxf(m, __shfl_xor_sync(0xffffffffu, m, o));

    __shared__ float sm_max[8], sm_sum[8];
    const int wid = tid >> 5, lid = tid & 31;
    if (lid == 0) sm_max[wid] = m;
    __syncthreads();
    float bm = sm_max[0];
#pragma unroll
    for (int i = 1; i < 8; i++) bm = fmaxf(bm, sm_max[i]);

    float s = 0.0f;
#pragma unroll
    for (int w = 0; w < 4; w++) {
        r[w].x = __expf(r[w].x - bm);
        r[w].y = __expf(r[w].y - bm);
        r[w].z = __expf(r[w].z - bm);
        r[w].w = __expf(r[w].w - bm);
        s += r[w].x + r[w].y + r[w].z + r[w].w;
    }
#pragma unroll
    for (int o = 16; o > 0; o >>= 1)
        s += __shfl_xor_sync(0xffffffffu, s, o);
    if (lid == 0) sm_sum[wid] = s;
    __syncthreads();
    float bs = 0.0f;
#pragma unroll
    for (int i = 0; i < 8; i++) bs += sm_sum[i];
    const float inv = 1.0f / bs;

#pragma unroll
    for (int w = 0; w < 4; w++) {
        float v0 = r[w].x * inv, v1 = r[w].y * inv, v2 = r[w].z * inv, v3 = r[w].w * inv;
        bf16 h0, h1, h2, h3, l0, l1, l2, l3;
        split_bf16(v0, h0, l0); split_bf16(v1, h1, l1);
        split_bf16(v2, h2, l2); split_bf16(v3, h3, l3);
        uint2 uh; uh.x = pack2(h0, h1); uh.y = pack2(h2, h3);
        uint2 ul; ul.x = pack2(l0, l1); ul.y = pack2(l2, l3);
        const size_t off = (size_t)row * TT + (size_t)(tid + w * 256) * 4;
        *reinterpret_cast<uint2*>(PH + off) = uh;
        *reinterpret_cast<uint2*>(PL + off) = ul;
    }
}

// ---------------------------------------------------------------------------
extern "C" void kernel_launch(void* const* d_in, const int* in_sizes, int n_in,
                              void* d_out, int out_size)
{
    (void)in_sizes; (void)n_in; (void)out_size;
    const float* x  = (const float*)d_in[0];
    const float* Wq = (const float*)d_in[1];
    const float* bq = (const float*)d_in[2];
    const float* Wk = (const float*)d_in[3];
    const float* bk = (const float*)d_in[4];
    const float* Wv = (const float*)d_in[5];
    const float* bv = (const float*)d_in[6];
    float* out = (float*)d_out;

    float *sp;
    bf16 *xh, *xl, *wh, *wl, *oh, *ol;
    cudaGetSymbolAddress((void**)&sp, g_s);
    cudaGetSymbolAddress((void**)&xh, g_xh);
    cudaGetSymbolAddress((void**)&xl, g_xl);
    cudaGetSymbolAddress((void**)&wh, g_wh);
    cudaGetSymbolAddress((void**)&wl, g_wl);
    cudaGetSymbolAddress((void**)&oh, g_oh);
    cudaGetSymbolAddress((void**)&ol, g_ol);

    cudaFuncSetAttribute(gemm_bf16x3_kernel<0>,
                         cudaFuncAttributeMaxDynamicSharedMemorySize, GEMM_SMEM);
    cudaFuncSetAttribute(gemm_bf16x3_kernel<1>,
                         cudaFuncAttributeMaxDynamicSharedMemorySize, GEMM_SMEM);

    const float scale = 1.0f / 64.0f;       // 1/sqrt(4096)

    // fused 3-way transpose+split of weights; split of x
    transpose_split3_kernel<<<dim3(TT / 32, TT / 32, 3), dim3(32, 8)>>>(Wq, Wk, Wv, wh, wl);
    convert_split_kernel<<<(unsigned)(SZ / 4 / 256), 256>>>(x, xh, xl);

    // fused q,k,v projections: z in {0,1,2}
    gemm_bf16x3_kernel<0><<<dim3(32, 32, 3), 256, GEMM_SMEM>>>(
        xh, xl, wh, wl, bq, bk, bv, 1.0f, nullptr, oh, ol);

    // S = scale * q @ k^T   (A = oh[0], B = oh[1])
    gemm_bf16x3_kernel<1><<<dim3(32, 32, 1), 256, GEMM_SMEM>>>(
        oh, ol, oh + SZ, ol + SZ, nullptr, nullptr, nullptr, scale,
        sp, nullptr, nullptr);

    // P = softmax_rows(S) -> overwrite q slab (oh[0]/ol[0])
    softmax_rows_kernel<<<TT, 256>>>(sp, oh, ol);

    // out = P @ v^T         (A = oh[0], B = oh[2])
    gemm_bf16x3_kernel<1><<<dim3(32, 32, 1), 256, GEMM_SMEM>>>(
        oh, ol, oh + 2 * SZ, ol + 2 * SZ, nullptr, nullptr, nullptr, 1.0f,
        out, nullptr, nullptr);
}

// round 16
// speedup vs baseline: 4.5264x; 1.3398x over previous
#include <cuda_runtime.h>
#include <cuda_fp16.h>
#include <stdint.h>
#include <math.h>

#define TT 4096
#define SZ ((size_t)TT * TT)
typedef __half fp16;

// ---------------------------------------------------------------------------
// Scratch (__device__ globals; no cudaMalloc allowed)
// ---------------------------------------------------------------------------
__device__ __align__(128) float g_s [SZ];        // scores fp32 (64MB)
__device__ __align__(128) fp16  g_xh[SZ];        // x as fp16 (unsplit A for proj)
__device__ __align__(128) fp16  g_wh[3][SZ];     // Wq^T,Wk^T,Wv^T hi
__device__ __align__(128) fp16  g_wl[3][SZ];     // lo
__device__ __align__(128) fp16  g_oh[3][SZ];     // q,k,v hi (q slab reused as P)
__device__ __align__(128) fp16  g_ol[3][SZ];     // q,k,v lo

// ---------------------------------------------------------------------------
// helpers
// ---------------------------------------------------------------------------
__device__ __forceinline__ uint32_t smem_to_u32(const void* p) {
    uint32_t a;
    asm("{ .reg .u64 t; cvta.to.shared.u64 t, %1; cvt.u32.u64 %0, t; }"
        : "=r"(a) : "l"(p));
    return a;
}
__device__ __forceinline__ uint32_t sw128(uint32_t bo) { return bo ^ ((bo >> 3) & 0x70); }

__device__ __forceinline__ void split_fp16(float v, fp16& h, fp16& l) {
    h = __float2half_rn(v);
    l = __float2half_rn(v - __half2float(h));
}
__device__ __forceinline__ uint32_t pack2(fp16 a, fp16 b) {
    return (uint32_t)__half_as_ushort(a) | ((uint32_t)__half_as_ushort(b) << 16);
}

#define CP_ASYNC16(saddr, gptr) \
    asm volatile("cp.async.cg.shared.global [%0], [%1], 16;" \
                 :: "r"(saddr), "l"(gptr) : "memory")
#define CP_COMMIT() asm volatile("cp.async.commit_group;" ::: "memory")
#define CP_WAIT1()  asm volatile("cp.async.wait_group 1;"  ::: "memory")
#define CP_WAIT2()  asm volatile("cp.async.wait_group 2;"  ::: "memory")

#define LDMATRIX_X4(r0, r1, r2, r3, addr) \
    asm volatile("ldmatrix.sync.aligned.m8n8.x4.shared.b16 {%0,%1,%2,%3}, [%4];" \
                 : "=r"(r0), "=r"(r1), "=r"(r2), "=r"(r3) : "r"(addr))

#define MMA_FP16(d, a, b0, b1) \
    asm volatile("mma.sync.aligned.m16n8k16.row.col.f32.f16.f16.f32 " \
                 "{%0,%1,%2,%3}, {%4,%5,%6,%7}, {%8,%9}, {%0,%1,%2,%3};" \
                 : "+f"((d)[0]), "+f"((d)[1]), "+f"((d)[2]), "+f"((d)[3]) \
                 : "r"((a)[0]), "r"((a)[1]), "r"((a)[2]), "r"((a)[3]), \
                   "r"(b0), "r"(b1))

// ---------------------------------------------------------------------------
// Elementwise convert: x fp32 -> xh fp16 (no split needed for 2-pass A side)
// ---------------------------------------------------------------------------
__global__ void __launch_bounds__(256)
convert_h_kernel(const float* __restrict__ X, fp16* __restrict__ H)
{
    size_t j = (size_t)blockIdx.x * blockDim.x + threadIdx.x;   // float4 index
    const float4 v = reinterpret_cast<const float4*>(X)[j];
    uint2 uh;
    uh.x = pack2(__float2half_rn(v.x), __float2half_rn(v.y));
    uh.y = pack2(__float2half_rn(v.z), __float2half_rn(v.w));
    reinterpret_cast<uint2*>(H)[j] = uh;
}

// ---------------------------------------------------------------------------
// Fused 3-way transpose + split: W[z] [K,N] fp32 -> WT hi/lo [N,K] fp16
// ---------------------------------------------------------------------------
__global__ void __launch_bounds__(256)
transpose_split3_kernel(const float* __restrict__ W0, const float* __restrict__ W1,
                        const float* __restrict__ W2,
                        fp16* __restrict__ THb, fp16* __restrict__ TLb)
{
    const int z = blockIdx.z;
    const float* W = (z == 0) ? W0 : (z == 1) ? W1 : W2;
    fp16* TH = THb + (size_t)z * SZ;
    fp16* TL = TLb + (size_t)z * SZ;

    __shared__ float t[32][33];
    const int tx = threadIdx.x, ty = threadIdx.y;     // 32 x 8
    const int n0 = blockIdx.x * 32, k0 = blockIdx.y * 32;
#pragma unroll
    for (int l = 0; l < 4; l++)
        t[ty + 8 * l][tx] = W[(size_t)(k0 + ty + 8 * l) * TT + n0 + tx];
    __syncthreads();
#pragma unroll
    for (int l = 0; l < 4; l++) {
        float v = t[tx][ty + 8 * l];
        fp16 h, lo; split_fp16(v, h, lo);
        size_t off = (size_t)(n0 + ty + 8 * l) * TT + k0 + tx;
        TH[off] = h; TL[off] = lo;
    }
}

// ---------------------------------------------------------------------------
// NT GEMM, fp16-split, mma.sync + cp.async pipeline.
//   C = alpha * (A @ B^T) (+ bias);  B/bias/C selected by blockIdx.z
//   NPASS=2: passes {Ah*Bh, Ah*Bl}; stage = {Ah, Bh, Bl}, 4 stages
//   NPASS=3: passes {Ah*Bh, Ah*Bl, Al*Bh}; stage = {Ah, Al, Bh, Bl}, 3 stages
//   MODE 0: C -> (Ch, Cl) fp16 split with bias added
//   MODE 1: C -> Cf fp32 scaled by alpha
// CTA tile 128x128, BK=64, 256 threads (8 warps, 4x2), warp tile 32x64.
// ---------------------------------------------------------------------------
#define TILE_B   16384           // 128 rows * 128B per operand tile
#define GEMM_SMEM 196608         // NPASS2: 4*3*TILE_B ; NPASS3: 3*4*TILE_B

template <int NPASS>
__device__ __forceinline__ void issue_stage_loads(
    const fp16* __restrict__ Ah, const fp16* __restrict__ Al,
    const fp16* __restrict__ Bh, const fp16* __restrict__ Bl,
    int bm0, int bn0, int k0, uint32_t stage_base, int tid)
{
    constexpr int NT = (NPASS == 3) ? 4 : 3;
    const fp16* srcs[4];
    int row0[4];
    if (NPASS == 3) {
        srcs[0] = Ah; srcs[1] = Al; srcs[2] = Bh; srcs[3] = Bl;
        row0[0] = bm0; row0[1] = bm0; row0[2] = bn0; row0[3] = bn0;
    } else {
        srcs[0] = Ah; srcs[1] = Bh; srcs[2] = Bl; srcs[3] = Bl;
        row0[0] = bm0; row0[1] = bn0; row0[2] = bn0; row0[3] = bn0;
    }
#pragma unroll
    for (int t = 0; t < NT; t++) {
        const fp16* G = srcs[t];
        const uint32_t tb = stage_base + t * TILE_B;
#pragma unroll
        for (int it = 0; it < 4; it++) {
            int idx = tid + it * 256;           // 0..1023
            int r = idx >> 3;                   // 0..127
            int c = idx & 7;                    // 16B chunk
            const fp16* gp = G + ((size_t)(row0[t] + r) << 12) + k0 + c * 8;
            uint32_t sa = tb + sw128((uint32_t)(r << 7) + (uint32_t)(c << 4));
            CP_ASYNC16(sa, gp);
        }
    }
}

template <int MODE, int NPASS>
__global__ void __launch_bounds__(256, 1)
gemm_fp16_kernel(const fp16* __restrict__ Ah, const fp16* __restrict__ Al,
                 const fp16* __restrict__ BhB, const fp16* __restrict__ BlB,
                 const float* __restrict__ bias0, const float* __restrict__ bias1,
                 const float* __restrict__ bias2, float alpha,
                 float* __restrict__ Cf, fp16* __restrict__ ChB, fp16* __restrict__ ClB)
{
    constexpr int NS    = (NPASS == 3) ? 3 : 4;                 // pipeline stages
    constexpr int NT    = (NPASS == 3) ? 4 : 3;                 // tiles per stage
    constexpr int STAGE = NT * TILE_B;
    constexpr uint32_t OFF_AL = TILE_B;                         // NPASS3 only
    constexpr uint32_t OFF_BH = (NPASS == 3) ? 2 * TILE_B : TILE_B;
    constexpr uint32_t OFF_BL = (NPASS == 3) ? 3 * TILE_B : 2 * TILE_B;

    extern __shared__ char smem[];
    const uint32_t sb = smem_to_u32(smem);
    const int tid  = threadIdx.x;
    const int wid  = tid >> 5;
    const int lane = tid & 31;

    const int z = blockIdx.z;
    const fp16* Bh = BhB + (size_t)z * SZ;
    const fp16* Bl = BlB + (size_t)z * SZ;
    const float* bias = (z == 0) ? bias0 : (z == 1) ? bias1 : bias2;
    fp16* Ch = (MODE == 0) ? (ChB + (size_t)z * SZ) : nullptr;
    fp16* Cl = (MODE == 0) ? (ClB + (size_t)z * SZ) : nullptr;

    // GROUP_M = 8 rasterization (grid is 32x32 per z-slice)
    const int bid = blockIdx.y * gridDim.x + blockIdx.x;     // 0..1023
    const int pm  = (bid >> 8) * 8 + (bid & 7);              // row tile
    const int pn  = (bid & 255) >> 3;                        // col tile
    const int bm0 = pm * 128, bn0 = pn * 128;

    const int wm = (wid & 3) * 32;        // warp m offset in tile
    const int wn = (wid >> 2) * 64;       // warp n offset in tile

    float acc[2][8][4];
#pragma unroll
    for (int mi = 0; mi < 2; mi++)
#pragma unroll
        for (int nj = 0; nj < 8; nj++)
#pragma unroll
            for (int e = 0; e < 4; e++) acc[mi][nj][e] = 0.0f;

    // prologue: stages 0 .. NS-2
#pragma unroll
    for (int s = 0; s < NS - 1; s++) {
        issue_stage_loads<NPASS>(Ah, Al, Bh, Bl, bm0, bn0, s * 64,
                                 sb + s * STAGE, tid);
        CP_COMMIT();
    }

    // per-lane ldmatrix address components
    const int a_row = (lane & 15);
    const int a_cb  = (lane >> 4) << 4;                 // 0 or 16
    const int b_row = (lane & 7) + ((lane >> 4) << 3);  // 0..15
    const int b_cb  = ((lane >> 3) & 1) << 4;           // 0 or 16

    // fragment double buffers
    uint32_t ah[2][2][4], al[2][2][4], bhf[2][4][4], blf[2][4][4];

    // fragment loader for one k16 step into buffer `buf`
    auto load_frags = [&](uint32_t stage, int ks, int buf) {
        const int kcb = ks * 32;
#pragma unroll
        for (int mi = 0; mi < 2; mi++) {
            const uint32_t ro = (uint32_t)((wm + mi * 16 + a_row) << 7);
            const uint32_t co = (uint32_t)(kcb + a_cb);
            LDMATRIX_X4(ah[buf][mi][0], ah[buf][mi][1], ah[buf][mi][2],
                        ah[buf][mi][3], stage + sw128(ro + co));
            if (NPASS == 3) {
                LDMATRIX_X4(al[buf][mi][0], al[buf][mi][1], al[buf][mi][2],
                            al[buf][mi][3], stage + OFF_AL + sw128(ro + co));
            }
        }
#pragma unroll
        for (int ni = 0; ni < 4; ni++) {
            const uint32_t ro = (uint32_t)((wn + ni * 16 + b_row) << 7);
            const uint32_t co = (uint32_t)(kcb + b_cb);
            LDMATRIX_X4(bhf[buf][ni][0], bhf[buf][ni][1], bhf[buf][ni][2],
                        bhf[buf][ni][3], stage + OFF_BH + sw128(ro + co));
            LDMATRIX_X4(blf[buf][ni][0], blf[buf][ni][1], blf[buf][ni][2],
                        blf[buf][ni][3], stage + OFF_BL + sw128(ro + co));
        }
    };

    // pass-major MMA block: dependent MMAs on the same acc are 16 issues apart
    auto mma_block = [&](int buf) {
#pragma unroll
        for (int mi = 0; mi < 2; mi++)
#pragma unroll
            for (int nj = 0; nj < 8; nj++) {
                const int ni = nj >> 1, s = (nj & 1) << 1;
                MMA_FP16(acc[mi][nj], ah[buf][mi],
                         bhf[buf][ni][s], bhf[buf][ni][s + 1]);
            }
#pragma unroll
        for (int mi = 0; mi < 2; mi++)
#pragma unroll
            for (int nj = 0; nj < 8; nj++) {
                const int ni = nj >> 1, s = (nj & 1) << 1;
                MMA_FP16(acc[mi][nj], ah[buf][mi],
                         blf[buf][ni][s], blf[buf][ni][s + 1]);
            }
        if (NPASS == 3) {
#pragma unroll
            for (int mi = 0; mi < 2; mi++)
#pragma unroll
                for (int nj = 0; nj < 8; nj++) {
                    const int ni = nj >> 1, s = (nj & 1) << 1;
                    MMA_FP16(acc[mi][nj], al[buf][mi],
                             bhf[buf][ni][s], bhf[buf][ni][s + 1]);
                }
        }
    };

    for (int c = 0; c < 64; c++) {
        if (NS == 4) { CP_WAIT2(); } else { CP_WAIT1(); }
        __syncthreads();       // single barrier per chunk

        if (c + NS - 1 < 64) {
            issue_stage_loads<NPASS>(Ah, Al, Bh, Bl, bm0, bn0, (c + NS - 1) * 64,
                                     sb + ((c + NS - 1) % NS) * STAGE, tid);
        }
        CP_COMMIT();

        const uint32_t stage = sb + (c % NS) * STAGE;

        load_frags(stage, 0, 0);
        load_frags(stage, 1, 1);
        mma_block(0);          // ks=0
        load_frags(stage, 2, 0);
        mma_block(1);          // ks=1
        load_frags(stage, 3, 1);
        mma_block(0);          // ks=2
        mma_block(1);          // ks=3
    }

    // ---- epilogue: direct stores from fragments ----
#pragma unroll
    for (int mi = 0; mi < 2; mi++) {
#pragma unroll
        for (int nj = 0; nj < 8; nj++) {
            const int row = bm0 + wm + mi * 16 + (lane >> 2);
            const int col = bn0 + wn + nj * 8 + (lane & 3) * 2;
            if (MODE == 0) {
                const float b0 = bias[col], b1 = bias[col + 1];
#pragma unroll
                for (int h = 0; h < 2; h++) {      // row, row+8
                    const float v0 = acc[mi][nj][2 * h + 0] + b0;
                    const float v1 = acc[mi][nj][2 * h + 1] + b1;
                    fp16 h0, h1, l0, l1;
                    split_fp16(v0, h0, l0); split_fp16(v1, h1, l1);
                    const size_t off = (size_t)(row + 8 * h) * TT + col;
                    *reinterpret_cast<uint32_t*>(Ch + off) = pack2(h0, h1);
                    *reinterpret_cast<uint32_t*>(Cl + off) = pack2(l0, l1);
                }
            } else {
#pragma unroll
                for (int h = 0; h < 2; h++) {
                    float2 v;
                    v.x = acc[mi][nj][2 * h + 0] * alpha;
                    v.y = acc[mi][nj][2 * h + 1] * alpha;
                    *reinterpret_cast<float2*>(Cf + (size_t)(row + 8 * h) * TT + col) = v;
                }
            }
        }
    }
}

// ---------------------------------------------------------------------------
// Row softmax over S [TT,TT] fp32; emits P as fp16 (unsplit — PV is 2-pass).
// ---------------------------------------------------------------------------
__global__ void __launch_bounds__(256)
softmax_rows_kernel(const float* __restrict__ S, fp16* __restrict__ PH)
{
    const int row = blockIdx.x;
    const float4* p = reinterpret_cast<const float4*>(S + (size_t)row * TT);
    const int tid = threadIdx.x;

    float4 r[4];
    float m = -3.402823466e38f;
#pragma unroll
    for (int w = 0; w < 4; w++) {
        r[w] = p[tid + w * 256];
        m = fmaxf(m, fmaxf(fmaxf(r[w].x, r[w].y), fmaxf(r[w].z, r[w].w)));
    }
#pragma unroll
    for (int o = 16; o > 0; o >>= 1)
        m = fmaxf(m, __shfl_xor_sync(0xffffffffu, m, o));

    __shared__ float sm_max[8], sm_sum[8];
    const int wid = tid >> 5, lid = tid & 31;
    if (lid == 0) sm_max[wid] = m;
    __syncthreads();
    float bm = sm_max[0];
#pragma unroll
    for (int i = 1; i < 8; i++) bm = fmaxf(bm, sm_max[i]);

    float s = 0.0f;
#pragma unroll
    for (int w = 0; w < 4; w++) {
        r[w].x = __expf(r[w].x - bm);
        r[w].y = __expf(r[w].y - bm);
        r[w].z = __expf(r[w].z - bm);
        r[w].w = __expf(r[w].w - bm);
        s += r[w].x + r[w].y + r[w].z + r[w].w;
    }
#pragma unroll
    for (int o = 16; o > 0; o >>= 1)
        s += __shfl_xor_sync(0xffffffffu, s, o);
    if (lid == 0) sm_sum[wid] = s;
    __syncthreads();
    float bs = 0.0f;
#pragma unroll
    for (int i = 0; i < 8; i++) bs += sm_sum[i];
    const float inv = 1.0f / bs;

#pragma unroll
    for (int w = 0; w < 4; w++) {
        uint2 uh;
        uh.x = pack2(__float2half_rn(r[w].x * inv), __float2half_rn(r[w].y * inv));
        uh.y = pack2(__float2half_rn(r[w].z * inv), __float2half_rn(r[w].w * inv));
        const size_t off = (size_t)row * TT + (size_t)(tid + w * 256) * 4;
        *reinterpret_cast<uint2*>(PH + off) = uh;
    }
}

// ---------------------------------------------------------------------------
extern "C" void kernel_launch(void* const* d_in, const int* in_sizes, int n_in,
                              void* d_out, int out_size)
{
    (void)in_sizes; (void)n_in; (void)out_size;
    const float* x  = (const float*)d_in[0];
    const float* Wq = (const float*)d_in[1];
    const float* bq = (const float*)d_in[2];
    const float* Wk = (const float*)d_in[3];
    const float* bk = (const float*)d_in[4];
    const float* Wv = (const float*)d_in[5];
    const float* bv = (const float*)d_in[6];
    float* out = (float*)d_out;

    float *sp;
    fp16 *xh, *wh, *wl, *oh, *ol;
    cudaGetSymbolAddress((void**)&sp, g_s);
    cudaGetSymbolAddress((void**)&xh, g_xh);
    cudaGetSymbolAddress((void**)&wh, g_wh);
    cudaGetSymbolAddress((void**)&wl, g_wl);
    cudaGetSymbolAddress((void**)&oh, g_oh);
    cudaGetSymbolAddress((void**)&ol, g_ol);

    cudaFuncSetAttribute((const void*)gemm_fp16_kernel<0, 2>,
                         cudaFuncAttributeMaxDynamicSharedMemorySize, GEMM_SMEM);
    cudaFuncSetAttribute((const void*)gemm_fp16_kernel<1, 3>,
                         cudaFuncAttributeMaxDynamicSharedMemorySize, GEMM_SMEM);
    cudaFuncSetAttribute((const void*)gemm_fp16_kernel<1, 2>,
                         cudaFuncAttributeMaxDynamicSharedMemorySize, GEMM_SMEM);

    const float scale = 1.0f / 64.0f;       // 1/sqrt(4096)

    // weight transpose+split (fp16 hi/lo); x -> fp16
    transpose_split3_kernel<<<dim3(TT / 32, TT / 32, 3), dim3(32, 8)>>>(Wq, Wk, Wv, wh, wl);
    convert_h_kernel<<<(unsigned)(SZ / 4 / 256), 256>>>(x, xh);

    // fused q,k,v projections (2-pass: x unsplit, W split), z in {0,1,2}
    gemm_fp16_kernel<0, 2><<<dim3(32, 32, 3), 256, GEMM_SMEM>>>(
        xh, nullptr, wh, wl, bq, bk, bv, 1.0f, nullptr, oh, ol);

    // S = scale * q @ k^T  (3-pass: q split, k split)
    gemm_fp16_kernel<1, 3><<<dim3(32, 32, 1), 256, GEMM_SMEM>>>(
        oh, ol, oh + SZ, ol + SZ, nullptr, nullptr, nullptr, scale,
        sp, nullptr, nullptr);

    // P = softmax_rows(S) -> overwrite q-hi slab (oh[0]), fp16 unsplit
    softmax_rows_kernel<<<TT, 256>>>(sp, oh);

    // out = P @ v^T  (2-pass: P unsplit, v split)
    gemm_fp16_kernel<1, 2><<<dim3(32, 32, 1), 256, GEMM_SMEM>>>(
        oh, nullptr, oh + 2 * SZ, ol + 2 * SZ, nullptr, nullptr, nullptr, 1.0f,
        out, nullptr, nullptr);
}

// round 17
// speedup vs baseline: 6.2743x; 1.3861x over previous
#include <cuda_runtime.h>
#include <cuda_fp16.h>
#include <stdint.h>
#include <math.h>

#define TT 4096
#define SZ ((size_t)TT * TT)
typedef __half fp16;

// ---------------------------------------------------------------------------
// Scratch (__device__ globals; no cudaMalloc allowed)
// ---------------------------------------------------------------------------
__device__ __align__(128) float g_s [SZ];        // scores fp32 (64MB)
__device__ __align__(128) fp16  g_xh[SZ];        // x as fp16 (unsplit)
__device__ __align__(128) fp16  g_wh[3][SZ];     // Wq^T,Wk^T,Wv^T hi only
__device__ __align__(128) fp16  g_oh[3][SZ];     // q,k,v hi (q slab reused as P)
__device__ __align__(128) fp16  g_ol[3][SZ];     // q,k,v lo (q,k used by scores)

// ---------------------------------------------------------------------------
// helpers
// ---------------------------------------------------------------------------
__device__ __forceinline__ uint32_t smem_to_u32(const void* p) {
    uint32_t a;
    asm("{ .reg .u64 t; cvta.to.shared.u64 t, %1; cvt.u32.u64 %0, t; }"
        : "=r"(a) : "l"(p));
    return a;
}
__device__ __forceinline__ uint32_t sw128(uint32_t bo) { return bo ^ ((bo >> 3) & 0x70); }

__device__ __forceinline__ void split_fp16(float v, fp16& h, fp16& l) {
    h = __float2half_rn(v);
    l = __float2half_rn(v - __half2float(h));
}
__device__ __forceinline__ uint32_t pack2(fp16 a, fp16 b) {
    return (uint32_t)__half_as_ushort(a) | ((uint32_t)__half_as_ushort(b) << 16);
}

#define CP_ASYNC16(saddr, gptr) \
    asm volatile("cp.async.cg.shared.global [%0], [%1], 16;" \
                 :: "r"(saddr), "l"(gptr) : "memory")
#define CP_COMMIT() asm volatile("cp.async.commit_group;" ::: "memory")

template <int N>
__device__ __forceinline__ void cp_wait() {
    asm volatile("cp.async.wait_group %0;" :: "n"(N) : "memory");
}

#define LDMATRIX_X4(r0, r1, r2, r3, addr) \
    asm volatile("ldmatrix.sync.aligned.m8n8.x4.shared.b16 {%0,%1,%2,%3}, [%4];" \
                 : "=r"(r0), "=r"(r1), "=r"(r2), "=r"(r3) : "r"(addr))

#define MMA_FP16(d, a, b0, b1) \
    asm volatile("mma.sync.aligned.m16n8k16.row.col.f32.f16.f16.f32 " \
                 "{%0,%1,%2,%3}, {%4,%5,%6,%7}, {%8,%9}, {%0,%1,%2,%3};" \
                 : "+f"((d)[0]), "+f"((d)[1]), "+f"((d)[2]), "+f"((d)[3]) \
                 : "r"((a)[0]), "r"((a)[1]), "r"((a)[2]), "r"((a)[3]), \
                   "r"(b0), "r"(b1))

// ---------------------------------------------------------------------------
// Elementwise convert: x fp32 -> xh fp16
// ---------------------------------------------------------------------------
__global__ void __launch_bounds__(256)
convert_h_kernel(const float* __restrict__ X, fp16* __restrict__ H)
{
    size_t j = (size_t)blockIdx.x * blockDim.x + threadIdx.x;   // float4 index
    const float4 v = reinterpret_cast<const float4*>(X)[j];
    uint2 uh;
    uh.x = pack2(__float2half_rn(v.x), __float2half_rn(v.y));
    uh.y = pack2(__float2half_rn(v.z), __float2half_rn(v.w));
    reinterpret_cast<uint2*>(H)[j] = uh;
}

// ---------------------------------------------------------------------------
// Fused 3-way transpose: W[z] [K,N] fp32 -> WT hi [N,K] fp16 (no lo needed)
// ---------------------------------------------------------------------------
__global__ void __launch_bounds__(256)
transpose_h3_kernel(const float* __restrict__ W0, const float* __restrict__ W1,
                    const float* __restrict__ W2, fp16* __restrict__ THb)
{
    const int z = blockIdx.z;
    const float* W = (z == 0) ? W0 : (z == 1) ? W1 : W2;
    fp16* TH = THb + (size_t)z * SZ;

    __shared__ float t[32][33];
    const int tx = threadIdx.x, ty = threadIdx.y;     // 32 x 8
    const int n0 = blockIdx.x * 32, k0 = blockIdx.y * 32;
#pragma unroll
    for (int l = 0; l < 4; l++)
        t[ty + 8 * l][tx] = W[(size_t)(k0 + ty + 8 * l) * TT + n0 + tx];
    __syncthreads();
#pragma unroll
    for (int l = 0; l < 4; l++) {
        float v = t[tx][ty + 8 * l];
        TH[(size_t)(n0 + ty + 8 * l) * TT + k0 + tx] = __float2half_rn(v);
    }
}

// ---------------------------------------------------------------------------
// NT GEMM, fp16-split, mma.sync + cp.async pipeline.
//   C = alpha * (A @ B^T) (+ bias);  B/bias/C selected by blockIdx.z
//   NPASS=1: {Ah*Bh};                 stage = {Ah, Bh},          6 stages
//   NPASS=2: {Ah*Bh, Ah*Bl};          stage = {Ah, Bh, Bl},      4 stages
//   NPASS=3: {Ah*Bh, Ah*Bl, Al*Bh};   stage = {Ah, Al, Bh, Bl},  3 stages
//   MODE 0: C -> (Ch, Cl) fp16 split with bias added
//   MODE 1: C -> Cf fp32 scaled by alpha
// CTA tile 128x128, BK=64, 256 threads (8 warps, 4x2), warp tile 32x64.
// ---------------------------------------------------------------------------
#define TILE_B   16384           // 128 rows * 128B per operand tile
#define GEMM_SMEM 196608         // = NS * NT * TILE_B for all NPASS configs

template <int NPASS>
__device__ __forceinline__ void issue_stage_loads(
    const fp16* __restrict__ Ah, const fp16* __restrict__ Al,
    const fp16* __restrict__ Bh, const fp16* __restrict__ Bl,
    int bm0, int bn0, int k0, uint32_t stage_base, int tid)
{
    constexpr int NT = (NPASS == 3) ? 4 : (NPASS == 2) ? 3 : 2;
    const fp16* srcs[4];
    int row0[4];
    if (NPASS == 3) {
        srcs[0] = Ah; srcs[1] = Al; srcs[2] = Bh; srcs[3] = Bl;
        row0[0] = bm0; row0[1] = bm0; row0[2] = bn0; row0[3] = bn0;
    } else if (NPASS == 2) {
        srcs[0] = Ah; srcs[1] = Bh; srcs[2] = Bl; srcs[3] = Bl;
        row0[0] = bm0; row0[1] = bn0; row0[2] = bn0; row0[3] = bn0;
    } else {
        srcs[0] = Ah; srcs[1] = Bh; srcs[2] = Bh; srcs[3] = Bh;
        row0[0] = bm0; row0[1] = bn0; row0[2] = bn0; row0[3] = bn0;
    }
#pragma unroll
    for (int t = 0; t < NT; t++) {
        const fp16* G = srcs[t];
        const uint32_t tb = stage_base + t * TILE_B;
#pragma unroll
        for (int it = 0; it < 4; it++) {
            int idx = tid + it * 256;           // 0..1023
            int r = idx >> 3;                   // 0..127
            int c = idx & 7;                    // 16B chunk
            const fp16* gp = G + ((size_t)(row0[t] + r) << 12) + k0 + c * 8;
            uint32_t sa = tb + sw128((uint32_t)(r << 7) + (uint32_t)(c << 4));
            CP_ASYNC16(sa, gp);
        }
    }
}

template <int MODE, int NPASS>
__global__ void __launch_bounds__(256, 1)
gemm_fp16_kernel(const fp16* __restrict__ Ah, const fp16* __restrict__ Al,
                 const fp16* __restrict__ BhB, const fp16* __restrict__ BlB,
                 const float* __restrict__ bias0, const float* __restrict__ bias1,
                 const float* __restrict__ bias2, float alpha,
                 float* __restrict__ Cf, fp16* __restrict__ ChB, fp16* __restrict__ ClB)
{
    constexpr int NS = (NPASS == 3) ? 3 : (NPASS == 2) ? 4 : 6;   // pipeline stages
    constexpr int NT = (NPASS == 3) ? 4 : (NPASS == 2) ? 3 : 2;   // tiles per stage
    constexpr int STAGE = NT * TILE_B;
    constexpr uint32_t OFF_AL = TILE_B;                           // NPASS3 only
    constexpr uint32_t OFF_BH = (NPASS == 3) ? 2 * TILE_B : TILE_B;
    constexpr uint32_t OFF_BL = (NPASS == 3) ? 3 * TILE_B : 2 * TILE_B;

    extern __shared__ char smem[];
    const uint32_t sb = smem_to_u32(smem);
    const int tid  = threadIdx.x;
    const int wid  = tid >> 5;
    const int lane = tid & 31;

    const int z = blockIdx.z;
    const fp16* Bh = BhB + (size_t)z * SZ;
    const fp16* Bl = (NPASS >= 2) ? (BlB + (size_t)z * SZ) : nullptr;
    const float* bias = (z == 0) ? bias0 : (z == 1) ? bias1 : bias2;
    fp16* Ch = (MODE == 0) ? (ChB + (size_t)z * SZ) : nullptr;
    fp16* Cl = (MODE == 0) ? (ClB + (size_t)z * SZ) : nullptr;

    // GROUP_M = 8 rasterization (grid is 32x32 per z-slice)
    const int bid = blockIdx.y * gridDim.x + blockIdx.x;     // 0..1023
    const int pm  = (bid >> 8) * 8 + (bid & 7);              // row tile
    const int pn  = (bid & 255) >> 3;                        // col tile
    const int bm0 = pm * 128, bn0 = pn * 128;

    const int wm = (wid & 3) * 32;        // warp m offset in tile
    const int wn = (wid >> 2) * 64;       // warp n offset in tile

    float acc[2][8][4];
#pragma unroll
    for (int mi = 0; mi < 2; mi++)
#pragma unroll
        for (int nj = 0; nj < 8; nj++)
#pragma unroll
            for (int e = 0; e < 4; e++) acc[mi][nj][e] = 0.0f;

    // prologue: stages 0 .. NS-2
#pragma unroll
    for (int s = 0; s < NS - 1; s++) {
        issue_stage_loads<NPASS>(Ah, Al, Bh, Bl, bm0, bn0, s * 64,
                                 sb + s * STAGE, tid);
        CP_COMMIT();
    }

    // per-lane ldmatrix address components
    const int a_row = (lane & 15);
    const int a_cb  = (lane >> 4) << 4;                 // 0 or 16
    const int b_row = (lane & 7) + ((lane >> 4) << 3);  // 0..15
    const int b_cb  = ((lane >> 3) & 1) << 4;           // 0 or 16

    // fragment double buffers
    uint32_t ah[2][2][4], al[2][2][4], bhf[2][4][4], blf[2][4][4];

    // fragment loader for one k16 step into buffer `buf`
    auto load_frags = [&](uint32_t stage, int ks, int buf) {
        const int kcb = ks * 32;
#pragma unroll
        for (int mi = 0; mi < 2; mi++) {
            const uint32_t ro = (uint32_t)((wm + mi * 16 + a_row) << 7);
            const uint32_t co = (uint32_t)(kcb + a_cb);
            LDMATRIX_X4(ah[buf][mi][0], ah[buf][mi][1], ah[buf][mi][2],
                        ah[buf][mi][3], stage + sw128(ro + co));
            if (NPASS == 3) {
                LDMATRIX_X4(al[buf][mi][0], al[buf][mi][1], al[buf][mi][2],
                            al[buf][mi][3], stage + OFF_AL + sw128(ro + co));
            }
        }
#pragma unroll
        for (int ni = 0; ni < 4; ni++) {
            const uint32_t ro = (uint32_t)((wn + ni * 16 + b_row) << 7);
            const uint32_t co = (uint32_t)(kcb + b_cb);
            LDMATRIX_X4(bhf[buf][ni][0], bhf[buf][ni][1], bhf[buf][ni][2],
                        bhf[buf][ni][3], stage + OFF_BH + sw128(ro + co));
            if (NPASS >= 2) {
                LDMATRIX_X4(blf[buf][ni][0], blf[buf][ni][1], blf[buf][ni][2],
                            blf[buf][ni][3], stage + OFF_BL + sw128(ro + co));
            }
        }
    };

    // pass-major MMA block: dependent MMAs on the same acc are 16 issues apart
    auto mma_block = [&](int buf) {
#pragma unroll
        for (int mi = 0; mi < 2; mi++)
#pragma unroll
            for (int nj = 0; nj < 8; nj++) {
                const int ni = nj >> 1, s = (nj & 1) << 1;
                MMA_FP16(acc[mi][nj], ah[buf][mi],
                         bhf[buf][ni][s], bhf[buf][ni][s + 1]);
            }
        if (NPASS >= 2) {
#pragma unroll
            for (int mi = 0; mi < 2; mi++)
#pragma unroll
                for (int nj = 0; nj < 8; nj++) {
                    const int ni = nj >> 1, s = (nj & 1) << 1;
                    MMA_FP16(acc[mi][nj], ah[buf][mi],
                             blf[buf][ni][s], blf[buf][ni][s + 1]);
                }
        }
        if (NPASS == 3) {
#pragma unroll
            for (int mi = 0; mi < 2; mi++)
#pragma unroll
                for (int nj = 0; nj < 8; nj++) {
                    const int ni = nj >> 1, s = (nj & 1) << 1;
                    MMA_FP16(acc[mi][nj], al[buf][mi],
                             bhf[buf][ni][s], bhf[buf][ni][s + 1]);
                }
        }
    };

    for (int c = 0; c < 64; c++) {
        cp_wait<NS - 2>();
        __syncthreads();       // single barrier per chunk

        if (c + NS - 1 < 64) {
            issue_stage_loads<NPASS>(Ah, Al, Bh, Bl, bm0, bn0, (c + NS - 1) * 64,
                                     sb + ((c + NS - 1) % NS) * STAGE, tid);
        }
        CP_COMMIT();

        const uint32_t stage = sb + (c % NS) * STAGE;

        load_frags(stage, 0, 0);
        load_frags(stage, 1, 1);
        mma_block(0);          // ks=0
        load_frags(stage, 2, 0);
        mma_block(1);          // ks=1
        load_frags(stage, 3, 1);
        mma_block(0);          // ks=2
        mma_block(1);          // ks=3
    }

    // ---- epilogue: direct stores from fragments ----
#pragma unroll
    for (int mi = 0; mi < 2; mi++) {
#pragma unroll
        for (int nj = 0; nj < 8; nj++) {
            const int row = bm0 + wm + mi * 16 + (lane >> 2);
            const int col = bn0 + wn + nj * 8 + (lane & 3) * 2;
            if (MODE == 0) {
                const float b0 = bias[col], b1 = bias[col + 1];
#pragma unroll
                for (int h = 0; h < 2; h++) {      // row, row+8
                    const float v0 = acc[mi][nj][2 * h + 0] + b0;
                    const float v1 = acc[mi][nj][2 * h + 1] + b1;
                    fp16 h0, h1, l0, l1;
                    split_fp16(v0, h0, l0); split_fp16(v1, h1, l1);
                    const size_t off = (size_t)(row + 8 * h) * TT + col;
                    *reinterpret_cast<uint32_t*>(Ch + off) = pack2(h0, h1);
                    *reinterpret_cast<uint32_t*>(Cl + off) = pack2(l0, l1);
                }
            } else {
#pragma unroll
                for (int h = 0; h < 2; h++) {
                    float2 v;
                    v.x = acc[mi][nj][2 * h + 0] * alpha;
                    v.y = acc[mi][nj][2 * h + 1] * alpha;
                    *reinterpret_cast<float2*>(Cf + (size_t)(row + 8 * h) * TT + col) = v;
                }
            }
        }
    }
}

// ---------------------------------------------------------------------------
// Row softmax over S [TT,TT] fp32; emits P as fp16 (unsplit — PV is 1-pass).
// ---------------------------------------------------------------------------
__global__ void __launch_bounds__(256)
softmax_rows_kernel(const float* __restrict__ S, fp16* __restrict__ PH)
{
    const int row = blockIdx.x;
    const float4* p = reinterpret_cast<const float4*>(S + (size_t)row * TT);
    const int tid = threadIdx.x;

    float4 r[4];
    float m = -3.402823466e38f;
#pragma unroll
    for (int w = 0; w < 4; w++) {
        r[w] = p[tid + w * 256];
        m = fmaxf(m, fmaxf(fmaxf(r[w].x, r[w].y), fmaxf(r[w].z, r[w].w)));
    }
#pragma unroll
    for (int o = 16; o > 0; o >>= 1)
        m = fmaxf(m, __shfl_xor_sync(0xffffffffu, m, o));

    __shared__ float sm_max[8], sm_sum[8];
    const int wid = tid >> 5, lid = tid & 31;
    if (lid == 0) sm_max[wid] = m;
    __syncthreads();
    float bm = sm_max[0];
#pragma unroll
    for (int i = 1; i < 8; i++) bm = fmaxf(bm, sm_max[i]);

    float s = 0.0f;
#pragma unroll
    for (int w = 0; w < 4; w++) {
        r[w].x = __expf(r[w].x - bm);
        r[w].y = __expf(r[w].y - bm);
        r[w].z = __expf(r[w].z - bm);
        r[w].w = __expf(r[w].w - bm);
        s += r[w].x + r[w].y + r[w].z + r[w].w;
    }
#pragma unroll
    for (int o = 16; o > 0; o >>= 1)
        s += __shfl_xor_sync(0xffffffffu, s, o);
    if (lid == 0) sm_sum[wid] = s;
    __syncthreads();
    float bs = 0.0f;
#pragma unroll
    for (int i = 0; i < 8; i++) bs += sm_sum[i];
    const float inv = 1.0f / bs;

#pragma unroll
    for (int w = 0; w < 4; w++) {
        uint2 uh;
        uh.x = pack2(__float2half_rn(r[w].x * inv), __float2half_rn(r[w].y * inv));
        uh.y = pack2(__float2half_rn(r[w].z * inv), __float2half_rn(r[w].w * inv));
        const size_t off = (size_t)row * TT + (size_t)(tid + w * 256) * 4;
        *reinterpret_cast<uint2*>(PH + off) = uh;
    }
}

// ---------------------------------------------------------------------------
extern "C" void kernel_launch(void* const* d_in, const int* in_sizes, int n_in,
                              void* d_out, int out_size)
{
    (void)in_sizes; (void)n_in; (void)out_size;
    const float* x  = (const float*)d_in[0];
    const float* Wq = (const float*)d_in[1];
    const float* bq = (const float*)d_in[2];
    const float* Wk = (const float*)d_in[3];
    const float* bk = (const float*)d_in[4];
    const float* Wv = (const float*)d_in[5];
    const float* bv = (const float*)d_in[6];
    float* out = (float*)d_out;

    float *sp;
    fp16 *xh, *wh, *oh, *ol;
    cudaGetSymbolAddress((void**)&sp, g_s);
    cudaGetSymbolAddress((void**)&xh, g_xh);
    cudaGetSymbolAddress((void**)&wh, g_wh);
    cudaGetSymbolAddress((void**)&oh, g_oh);
    cudaGetSymbolAddress((void**)&ol, g_ol);

    cudaFuncSetAttribute((const void*)gemm_fp16_kernel<0, 1>,
                         cudaFuncAttributeMaxDynamicSharedMemorySize, GEMM_SMEM);
    cudaFuncSetAttribute((const void*)gemm_fp16_kernel<1, 3>,
                         cudaFuncAttributeMaxDynamicSharedMemorySize, GEMM_SMEM);
    cudaFuncSetAttribute((const void*)gemm_fp16_kernel<1, 1>,
                         cudaFuncAttributeMaxDynamicSharedMemorySize, GEMM_SMEM);

    const float scale = 1.0f / 64.0f;       // 1/sqrt(4096)

    // weight transpose (hi only); x -> fp16
    transpose_h3_kernel<<<dim3(TT / 32, TT / 32, 3), dim3(32, 8)>>>(Wq, Wk, Wv, wh);
    convert_h_kernel<<<(unsigned)(SZ / 4 / 256), 256>>>(x, xh);

    // fused q,k,v projections (1-pass: xh * Wh; fp32 acc split in epilogue)
    gemm_fp16_kernel<0, 1><<<dim3(32, 32, 3), 256, GEMM_SMEM>>>(
        xh, nullptr, wh, nullptr, bq, bk, bv, 1.0f, nullptr, oh, ol);

    // S = scale * q @ k^T  (3-pass: q split, k split — precision-critical)
    gemm_fp16_kernel<1, 3><<<dim3(32, 32, 1), 256, GEMM_SMEM>>>(
        oh, ol, oh + SZ, ol + SZ, nullptr, nullptr, nullptr, scale,
        sp, nullptr, nullptr);

    // P = softmax_rows(S) -> overwrite q-hi slab (oh[0]), fp16 unsplit
    softmax_rows_kernel<<<TT, 256>>>(sp, oh);

    // out = P @ v^T  (1-pass: P fp16 * v-hi fp16)
    gemm_fp16_kernel<1, 1><<<dim3(32, 32, 1), 256, GEMM_SMEM>>>(
        oh, nullptr, oh + 2 * SZ, nullptr, nullptr, nullptr, nullptr, 1.0f,
        out, nullptr, nullptr);
}